// round 16
// baseline (speedup 1.0000x reference)
#include <cuda_runtime.h>
#include <cuda_bf16.h>
#include <stdint.h>

// GCN 2-layer, atomic-scatter formulation with deferred normalization:
//   raw  = x @ W1                        (no dinv; overlapped with degree count)
//   dinv = rsqrt(indeg+1)
//   acc[d] = dinv[d]*raw[d] + sum_{e:dst=d} dinv[s]*raw[s]
//   h = relu(dinv[d]*acc[d] + b1);  g2 = dinv*(h@W2);  out = scatter(g2) etc.

#define NMAX 100096
#define F_IN 128
#define H1 32
#define H2 16

__device__ float g_cnt[NMAX];         // edge in-degree (float)
__device__ float g_dinv[NMAX];
__device__ float g_g1[NMAX * H1];     // RAW x@W1 (un-normalized)
__device__ float g_acc1[NMAX * H1];
__device__ float g_g2[NMAX * H2];

// ---------------------------------------------------------------- helpers ----
__global__ void k_zero_deg(int n) {
    int i = blockIdx.x * blockDim.x + threadIdx.x;
    if (i < n) g_cnt[i] = 0.0f;
}

// ------------------------------------------------ fused degree-count + GEMM --
// Interleaved grid partition: every S-th block is a GEMM block (gi = bid/S,
// gi < GB); all others are degree-count blocks. The two halves touch disjoint
// data and bind different pipes (FMA/LSU vs LTS-RED), so they overlap.
// GEMM: thread = 8 contiguous rows x 4 cols, writes RAW product to g_g1.
__global__ void __launch_bounds__(256, 3) k_gemm1_count(
        const float* __restrict__ x, const float* __restrict__ W1,
        const int* __restrict__ dst, int n, int E, int GB, int S) {
    __shared__ float Ws[F_IN * H1];   // 16 KB (unused by count blocks)
    int bid = blockIdx.x;
    int tid = threadIdx.x;

    if (bid % S == 0 && bid / S < GB) {
        // ---------------- GEMM block ----------------
        int gi = bid / S;
        for (int i = tid; i < F_IN * H1; i += 256) Ws[i] = W1[i];
        __syncthreads();

        int lane = tid & 31, warp = tid >> 5;
        int c0 = (lane & 7) * 4;
        int rg = lane >> 3;
        int rowbase = gi * 256 + warp * 32 + rg * 8;

        const float* xb = x + (size_t)rowbase * F_IN;
        int nr = n - rowbase;

        float acc[8][4] = {};
#pragma unroll
        for (int k4 = 0; k4 < F_IN; k4 += 4) {
            float4 xv[8];
#pragma unroll
            for (int r = 0; r < 8; r++) {
                xv[r] = (r < nr) ? __ldg((const float4*)(xb + r * F_IN + k4))
                                 : make_float4(0.f, 0.f, 0.f, 0.f);
            }
            float4 w0 = *(const float4*)&Ws[(k4 + 0) * H1 + c0];
            float4 w1 = *(const float4*)&Ws[(k4 + 1) * H1 + c0];
            float4 w2 = *(const float4*)&Ws[(k4 + 2) * H1 + c0];
            float4 w3 = *(const float4*)&Ws[(k4 + 3) * H1 + c0];
#pragma unroll
            for (int r = 0; r < 8; r++) {
                acc[r][0] = fmaf(xv[r].x, w0.x, acc[r][0]);
                acc[r][1] = fmaf(xv[r].x, w0.y, acc[r][1]);
                acc[r][2] = fmaf(xv[r].x, w0.z, acc[r][2]);
                acc[r][3] = fmaf(xv[r].x, w0.w, acc[r][3]);
                acc[r][0] = fmaf(xv[r].y, w1.x, acc[r][0]);
                acc[r][1] = fmaf(xv[r].y, w1.y, acc[r][1]);
                acc[r][2] = fmaf(xv[r].y, w1.z, acc[r][2]);
                acc[r][3] = fmaf(xv[r].y, w1.w, acc[r][3]);
                acc[r][0] = fmaf(xv[r].z, w2.x, acc[r][0]);
                acc[r][1] = fmaf(xv[r].z, w2.y, acc[r][1]);
                acc[r][2] = fmaf(xv[r].z, w2.z, acc[r][2]);
                acc[r][3] = fmaf(xv[r].z, w2.w, acc[r][3]);
                acc[r][0] = fmaf(xv[r].w, w3.x, acc[r][0]);
                acc[r][1] = fmaf(xv[r].w, w3.y, acc[r][1]);
                acc[r][2] = fmaf(xv[r].w, w3.z, acc[r][2]);
                acc[r][3] = fmaf(xv[r].w, w3.w, acc[r][3]);
            }
        }
#pragma unroll
        for (int r = 0; r < 8; r++) {
            int row = rowbase + r;
            if (row < n) {
                *(float4*)&g_g1[row * H1 + c0] =
                    make_float4(acc[r][0], acc[r][1], acc[r][2], acc[r][3]);
            }
        }
    } else {
        // ---------------- degree-count block ----------------
        int ng = (bid == 0) ? 0 : min((bid - 1) / S + 1, GB);  // gemm blocks < bid
        int e = (bid - ng) * 256 + tid;
        if (e < E) atomicAdd(&g_cnt[dst[e]], 1.0f);  // no-return -> RED
    }
}

// dinv + self-loop seed: acc1[d] = dinv[d] * raw[d]; stores dinv.
__global__ void k_selfinit(int total8) {   // total8 = n * 8 (8 quads per row)
    int i = blockIdx.x * blockDim.x + threadIdx.x;
    if (i < total8) {
        int row = i >> 3, q = i & 7;
        float di = rsqrtf(g_cnt[row] + 1.0f);   // +1 = self loop
        if (q == 0) g_dinv[row] = di;
        float4 v = ((const float4*)(g_g1 + row * H1))[q];
        v.x *= di; v.y *= di; v.z *= di; v.w *= di;
        ((float4*)(g_acc1 + row * H1))[q] = v;
    }
}

// per-edge scatter: acc1[dst] += dinv[src] * raw[src]  (8 x red.v4 per edge)
__global__ void k_scatter1(const int* __restrict__ src, const int* __restrict__ dst, int E) {
    long long tid = (long long)blockIdx.x * blockDim.x + threadIdx.x;
    if (tid >= (long long)E * 8) return;
    int e = (int)(tid >> 3), c = (int)(tid & 7);
    int s = __ldg(&src[e]);
    int d = __ldg(&dst[e]);
    float ds = __ldg(&g_dinv[s]);
    float4 v = ((const float4*)(g_g1 + s * H1))[c];
    v.x *= ds; v.y *= ds; v.z *= ds; v.w *= ds;
    float* p = g_acc1 + d * H1 + c * 4;
    asm volatile("red.global.add.v4.f32 [%0], {%1,%2,%3,%4};"
                 :: "l"(p), "f"(v.x), "f"(v.y), "f"(v.z), "f"(v.w) : "memory");
}

// epilogue layer1 + GEMM2 fused (warp shuffles), writes g2 and out self-loop.
__global__ void k_finish1_gemm2(const float* __restrict__ W2, const float* __restrict__ b1,
                                float* __restrict__ out, int n) {
    __shared__ float W2s[H1 * H2];  // 2 KB
    __shared__ float b1s[H1];
    int tid = threadIdx.x;  // 256
    for (int i = tid; i < H1 * H2; i += 256) W2s[i] = W2[i];
    if (tid < H1) b1s[tid] = b1[tid];
    __syncthreads();

    int warp = tid >> 5, lane = tid & 31;
    int row = blockIdx.x * 8 + warp;
    if (row >= n) return;

    float di = g_dinv[row];
    float h = fmaxf(fmaf(di, g_acc1[row * H1 + lane], b1s[lane]), 0.0f);

    float acc = 0.0f;
    int j = lane & 15;
#pragma unroll
    for (int k = 0; k < H1; k++) {
        float v = __shfl_sync(0xffffffffu, h, k);
        acc = fmaf(v, W2s[k * H2 + j], acc);
    }
    if (lane < H2) {
        float g = acc * di;
        g_g2[row * H2 + lane] = g;
        out[row * H2 + lane]  = g;
    }
}

// per-edge scatter layer 2: out[dst] += g2[src]  (4 x red.v4 per edge)
__global__ void k_scatter2(const int* __restrict__ src, const int* __restrict__ dst,
                           float* __restrict__ out, int E) {
    long long tid = (long long)blockIdx.x * blockDim.x + threadIdx.x;
    if (tid >= (long long)E * 4) return;
    int e = (int)(tid >> 2), c = (int)(tid & 3);
    int s = __ldg(&src[e]);
    int d = __ldg(&dst[e]);
    float4 v = ((const float4*)(g_g2 + s * H2))[c];
    float* p = out + d * H2 + c * 4;
    asm volatile("red.global.add.v4.f32 [%0], {%1,%2,%3,%4};"
                 :: "l"(p), "f"(v.x), "f"(v.y), "f"(v.z), "f"(v.w) : "memory");
}

// vectorized: thread handles 4 consecutive outputs (quarter-row of H2=16)
__global__ void k_finish2(float* __restrict__ out, const float* __restrict__ b2, int nquads) {
    int i = blockIdx.x * blockDim.x + threadIdx.x;
    if (i < nquads) {
        int row = i >> 2;
        int q = (i & 3) * 4;
        float di = g_dinv[row];
        float4 b = *(const float4*)&b2[q];
        float4 v = *(float4*)&out[row * H2 + q];
        v.x = fmaf(di, v.x, b.x);
        v.y = fmaf(di, v.y, b.y);
        v.z = fmaf(di, v.z, b.z);
        v.w = fmaf(di, v.w, b.w);
        *(float4*)&out[row * H2 + q] = v;
    }
}

// ------------------------------------------------------------------ host ----
extern "C" void kernel_launch(void* const* d_in, const int* in_sizes, int n_in,
                              void* d_out, int out_size) {
    const float* x  = (const float*)d_in[0];
    const int*   ei = (const int*)d_in[1];
    const float* W1 = (const float*)d_in[2];
    const float* b1 = (const float*)d_in[3];
    const float* W2 = (const float*)d_in[4];
    const float* b2 = (const float*)d_in[5];
    float* out = (float*)d_out;

    int n = in_sizes[0] / F_IN;   // 100000
    int E = in_sizes[1] / 2;      // 3200000
    const int* src = ei;
    const int* dst = ei + E;

    int GB = (n + 255) / 256;     // gemm blocks   (391)
    int CB = (E + 255) / 256;     // count blocks  (12500)
    int S  = CB / GB + 1;         // interleave stride (33)

    k_zero_deg<<<(n + 255) / 256, 256>>>(n);
    k_gemm1_count<<<GB + CB, 256>>>(x, W1, dst, n, E, GB, S);
    k_selfinit<<<(n * 8 + 255) / 256, 256>>>(n * 8);
    k_scatter1<<<(int)(((long long)E * 8 + 255) / 256), 256>>>(src, dst, E);
    k_finish1_gemm2<<<(n + 7) / 8, 256>>>(W2, b1, out, n);
    k_scatter2<<<(int)(((long long)E * 4 + 255) / 256), 256>>>(src, dst, out, E);
    k_finish2<<<(n * 4 + 255) / 256, 256>>>(out, b2, n * 4);
}

// round 17
// speedup vs baseline: 1.0433x; 1.0433x over previous
#include <cuda_runtime.h>
#include <cuda_bf16.h>
#include <stdint.h>

// GCN 2-layer, atomic-scatter, deferred normalization + fused degree count:
//   raw  = x @ W1            (g_g1; count-REDs fired from same kernel)
//   dinv = rsqrt(cnt+1)      (recomputed on the fly; no dinv array)
//   acc1[d] = sum_{e:dst=d} dinv[s]*raw[s]         (acc1 zero-seeded by gemm)
//   h = relu(dinv*acc1 + dinv^2*raw + b1); g2 = dinv*(h@W2); layer2 likewise.

#define NMAX 100096
#define F_IN 128
#define H1 32
#define H2 16

__device__ float g_cnt[NMAX];         // edge in-degree (float)
__device__ float g_g1[NMAX * H1];     // RAW x@W1
__device__ float g_acc1[NMAX * H1];
__device__ float g_g2[NMAX * H2];

__global__ void k_zero_deg(int n) {
    int i = blockIdx.x * blockDim.x + threadIdx.x;
    if (i < n) g_cnt[i] = 0.0f;
}

// ------------------------------------------- GEMM + fire-and-forget count ---
// Thread = 8 contiguous rows x 4 cols (proven R15 tile). Before the matmul,
// each thread streams its grid-stride share of degree-count REDs (no return
// value -> no stall chain; LTS absorbs them under the FMA-bound matmul).
__global__ void __launch_bounds__(256, 3) k_gemm1c(const float* __restrict__ x,
                                                   const float* __restrict__ W1,
                                                   const int* __restrict__ dst,
                                                   int n, int E) {
    __shared__ float Ws[F_IN * H1];   // 16 KB
    int tid = threadIdx.x;
    int gsz = gridDim.x * 256;

    // count phase: coalesced dst reads, fire REDs, move on
    for (int e = blockIdx.x * 256 + tid; e < E; e += gsz)
        atomicAdd(&g_cnt[__ldg(&dst[e])], 1.0f);

    for (int i = tid; i < F_IN * H1; i += 256) Ws[i] = W1[i];
    __syncthreads();

    int lane = tid & 31, warp = tid >> 5;
    int c0 = (lane & 7) * 4;
    int rg = lane >> 3;
    int rowbase = blockIdx.x * 256 + warp * 32 + rg * 8;

    const float* xb = x + (size_t)rowbase * F_IN;
    int nr = n - rowbase;

    float acc[8][4] = {};
#pragma unroll
    for (int k4 = 0; k4 < F_IN; k4 += 4) {
        float4 xv[8];
#pragma unroll
        for (int r = 0; r < 8; r++) {
            xv[r] = (r < nr) ? __ldg((const float4*)(xb + r * F_IN + k4))
                             : make_float4(0.f, 0.f, 0.f, 0.f);
        }
        float4 w0 = *(const float4*)&Ws[(k4 + 0) * H1 + c0];
        float4 w1 = *(const float4*)&Ws[(k4 + 1) * H1 + c0];
        float4 w2 = *(const float4*)&Ws[(k4 + 2) * H1 + c0];
        float4 w3 = *(const float4*)&Ws[(k4 + 3) * H1 + c0];
#pragma unroll
        for (int r = 0; r < 8; r++) {
            acc[r][0] = fmaf(xv[r].x, w0.x, acc[r][0]);
            acc[r][1] = fmaf(xv[r].x, w0.y, acc[r][1]);
            acc[r][2] = fmaf(xv[r].x, w0.z, acc[r][2]);
            acc[r][3] = fmaf(xv[r].x, w0.w, acc[r][3]);
            acc[r][0] = fmaf(xv[r].y, w1.x, acc[r][0]);
            acc[r][1] = fmaf(xv[r].y, w1.y, acc[r][1]);
            acc[r][2] = fmaf(xv[r].y, w1.z, acc[r][2]);
            acc[r][3] = fmaf(xv[r].y, w1.w, acc[r][3]);
            acc[r][0] = fmaf(xv[r].z, w2.x, acc[r][0]);
            acc[r][1] = fmaf(xv[r].z, w2.y, acc[r][1]);
            acc[r][2] = fmaf(xv[r].z, w2.z, acc[r][2]);
            acc[r][3] = fmaf(xv[r].z, w2.w, acc[r][3]);
            acc[r][0] = fmaf(xv[r].w, w3.x, acc[r][0]);
            acc[r][1] = fmaf(xv[r].w, w3.y, acc[r][1]);
            acc[r][2] = fmaf(xv[r].w, w3.z, acc[r][2]);
            acc[r][3] = fmaf(xv[r].w, w3.w, acc[r][3]);
        }
    }

    float4 z4 = make_float4(0.f, 0.f, 0.f, 0.f);
#pragma unroll
    for (int r = 0; r < 8; r++) {
        int row = rowbase + r;
        if (row < n) {
            *(float4*)&g_g1[row * H1 + c0] =
                make_float4(acc[r][0], acc[r][1], acc[r][2], acc[r][3]);
            *(float4*)&g_acc1[row * H1 + c0] = z4;   // zero-seed for scatter
        }
    }
}

// per-edge scatter: acc1[dst] += rsqrt(cnt[src]+1) * raw[src]
__global__ void k_scatter1(const int* __restrict__ src, const int* __restrict__ dst, int E) {
    long long tid = (long long)blockIdx.x * blockDim.x + threadIdx.x;
    if (tid >= (long long)E * 8) return;
    int e = (int)(tid >> 3), c = (int)(tid & 7);
    int s = __ldg(&src[e]);
    int d = __ldg(&dst[e]);
    float ds = rsqrtf(__ldg(&g_cnt[s]) + 1.0f);
    float4 v = ((const float4*)(g_g1 + s * H1))[c];
    v.x *= ds; v.y *= ds; v.z *= ds; v.w *= ds;
    float* p = g_acc1 + d * H1 + c * 4;
    asm volatile("red.global.add.v4.f32 [%0], {%1,%2,%3,%4};"
                 :: "l"(p), "f"(v.x), "f"(v.y), "f"(v.z), "f"(v.w) : "memory");
}

// finish layer1 (+ self loop di^2*raw) + GEMM2 fused; writes g2 + out seed.
__global__ void k_finish1_gemm2(const float* __restrict__ W2, const float* __restrict__ b1,
                                float* __restrict__ out, int n) {
    __shared__ float W2s[H1 * H2];
    __shared__ float b1s[H1];
    int tid = threadIdx.x;  // 256
    for (int i = tid; i < H1 * H2; i += 256) W2s[i] = W2[i];
    if (tid < H1) b1s[tid] = b1[tid];
    __syncthreads();

    int warp = tid >> 5, lane = tid & 31;
    int row = blockIdx.x * 8 + warp;
    if (row >= n) return;

    float di  = rsqrtf(__ldg(&g_cnt[row]) + 1.0f);
    float a   = g_acc1[row * H1 + lane];
    float raw = g_g1[row * H1 + lane];
    float h = fmaxf(fmaf(di, a, di * di * raw) + b1s[lane], 0.0f);

    float acc = 0.0f;
    int j = lane & 15;
#pragma unroll
    for (int k = 0; k < H1; k++) {
        float v = __shfl_sync(0xffffffffu, h, k);
        acc = fmaf(v, W2s[k * H2 + j], acc);
    }
    if (lane < H2) {
        float g = acc * di;
        g_g2[row * H2 + lane] = g;
        out[row * H2 + lane]  = g;
    }
}

// per-edge scatter layer 2: out[dst] += g2[src]  (4 x red.v4 per edge)
__global__ void k_scatter2(const int* __restrict__ src, const int* __restrict__ dst,
                           float* __restrict__ out, int E) {
    long long tid = (long long)blockIdx.x * blockDim.x + threadIdx.x;
    if (tid >= (long long)E * 4) return;
    int e = (int)(tid >> 2), c = (int)(tid & 3);
    int s = __ldg(&src[e]);
    int d = __ldg(&dst[e]);
    float4 v = ((const float4*)(g_g2 + s * H2))[c];
    float* p = out + d * H2 + c * 4;
    asm volatile("red.global.add.v4.f32 [%0], {%1,%2,%3,%4};"
                 :: "l"(p), "f"(v.x), "f"(v.y), "f"(v.z), "f"(v.w) : "memory");
}

// thread = 4 consecutive outputs (quarter-row of H2=16)
__global__ void k_finish2(float* __restrict__ out, const float* __restrict__ b2, int nquads) {
    int i = blockIdx.x * blockDim.x + threadIdx.x;
    if (i < nquads) {
        int row = i >> 2;
        int q = (i & 3) * 4;
        float di = rsqrtf(__ldg(&g_cnt[row]) + 1.0f);
        float4 b = *(const float4*)&b2[q];
        float4 v = *(float4*)&out[row * H2 + q];
        v.x = fmaf(di, v.x, b.x);
        v.y = fmaf(di, v.y, b.y);
        v.z = fmaf(di, v.z, b.z);
        v.w = fmaf(di, v.w, b.w);
        *(float4*)&out[row * H2 + q] = v;
    }
}

// ------------------------------------------------------------------ host ----
extern "C" void kernel_launch(void* const* d_in, const int* in_sizes, int n_in,
                              void* d_out, int out_size) {
    const float* x  = (const float*)d_in[0];
    const int*   ei = (const int*)d_in[1];
    const float* W1 = (const float*)d_in[2];
    const float* b1 = (const float*)d_in[3];
    const float* W2 = (const float*)d_in[4];
    const float* b2 = (const float*)d_in[5];
    float* out = (float*)d_out;

    int n = in_sizes[0] / F_IN;   // 100000
    int E = in_sizes[1] / 2;      // 3200000
    const int* src = ei;
    const int* dst = ei + E;

    k_zero_deg<<<(n + 255) / 256, 256>>>(n);
    k_gemm1c<<<(n + 255) / 256, 256>>>(x, W1, dst, n, E);
    k_scatter1<<<(int)(((long long)E * 8 + 255) / 256), 256>>>(src, dst, E);
    k_finish1_gemm2<<<(n + 7) / 8, 256>>>(W2, b1, out, n);
    k_scatter2<<<(int)(((long long)E * 4 + 255) / 256), 256>>>(src, dst, out, E);
    k_finish2<<<(n * 4 + 255) / 256, 256>>>(out, b2, n * 4);
}